// round 14
// baseline (speedup 1.0000x reference)
#include <cuda_runtime.h>

#define NN   50
#define PP   32
#define BB   512
#define NSQ  2500
#define FSTRIDE 54          // float2 stride 27, gcd(27,16)=1 -> conflict-free LDS.64
#define MAIN_THREADS 800    // 16 units * 50 rows per round, 2 rounds

__device__ __forceinline__ float ex2_approx(float x) {
    float r;
    asm("ex2.approx.f32 %0, %1;" : "=f"(r) : "f"(x));
    return r;
}

// ---------------------------------------------------------------------------
// K1 v4: F[r] = sum_j g[r,j] * w[j]^2.  One warp per row.
// Two batches of 10 LDG.128; batch 1 fully unpredicated (indices < 320 < 625),
// batch 2 predicated only in its last chunk. Row pitch 10000 B -> float4 ok.
// ---------------------------------------------------------------------------
__global__ __launch_bounds__(256)
void f_matvec_kernel(const float* __restrict__ g,
                     const float* __restrict__ w,
                     float* __restrict__ Fout) {
    __shared__ float4 w2s[625];
    int tid  = threadIdx.x;
    int lane = tid & 31;
    int wid  = tid >> 5;

    const float4* w4 = (const float4*)w;
    for (int j = tid; j < 625; j += 256) {
        float4 wv = w4[j];
        w2s[j] = make_float4(wv.x * wv.x, wv.y * wv.y, wv.z * wv.z, wv.w * wv.w);
    }
    __syncthreads();

    int row = blockIdx.x * 8 + wid;
    if (row >= NSQ) return;
    const float4* grow = (const float4*)g + (size_t)row * 625;

    float4 r[10];
    float acc = 0.f;

    // Batch 1: idx = lane + 32k, k=0..9  (max 319) -- no predication
    #pragma unroll
    for (int k = 0; k < 10; k++) r[k] = grow[lane + 32 * k];
    #pragma unroll
    for (int k = 0; k < 10; k++) {
        float4 wv = w2s[lane + 32 * k];
        acc = fmaf(r[k].x, wv.x, acc);
        acc = fmaf(r[k].y, wv.y, acc);
        acc = fmaf(r[k].z, wv.z, acc);
        acc = fmaf(r[k].w, wv.w, acc);
    }

    // Batch 2: idx = 320 + lane + 32k, k=0..9 (max 639); only k=9 partially OOB
    #pragma unroll
    for (int k = 0; k < 10; k++) {
        int idx = 320 + lane + 32 * k;
        r[k] = (idx < 625) ? grow[idx] : make_float4(0.f, 0.f, 0.f, 0.f);
    }
    #pragma unroll
    for (int k = 0; k < 10; k++) {
        int idx = 320 + lane + 32 * k;
        float4 wv = (idx < 625) ? w2s[idx] : make_float4(0.f, 0.f, 0.f, 0.f);
        acc = fmaf(r[k].x, wv.x, acc);
        acc = fmaf(r[k].y, wv.y, acc);
        acc = fmaf(r[k].z, wv.z, acc);
        acc = fmaf(r[k].w, wv.w, acc);
    }

    #pragma unroll
    for (int o = 16; o > 0; o >>= 1)
        acc += __shfl_down_sync(0xffffffffu, acc, o);
    if (lane == 0) Fout[row] = acc;
}

// ---------------------------------------------------------------------------
// Main fused kernel: one block per batch element b (512 blocks, 800 threads).
// Covers all 32 (b,p) units; Z written directly incl. 32*mu_y (no K2, no atomics).
//   z[u][i] = sum_j exp2(na_u * F[i,j]) * a_u[j] / sum_j exp2(na_u * F[i,j])
//   a_u[j]  = x[b,j,u] - mus[t_u,j],  t_u = x_i[b,u]
// ---------------------------------------------------------------------------
__global__ __launch_bounds__(MAIN_THREADS, 2)
void main_kernel(const float* __restrict__ x,
                 const int*   __restrict__ x_i,
                 const int*   __restrict__ y_i,
                 const float* __restrict__ mus,
                 const float* __restrict__ alphas,
                 const float* __restrict__ F,
                 float* __restrict__ Z) {
    __shared__ float Fs[NN * FSTRIDE];                  // padded F
    __shared__ float Xs[NN][33];                        // x[b] slice, padded
    __shared__ __align__(8) float As[PP][52];           // a vectors
    __shared__ __align__(8) float zmat[PP][52];         // per-unit z rows
    __shared__ float nal[PP];
    __shared__ int   ts[PP];

    int tid = threadIdx.x;
    int b   = blockIdx.x;

    // F -> smem (padded rows)
    for (int k = tid; k < NSQ; k += MAIN_THREADS) {
        int i = k / NN;
        int j = k - i * NN;
        Fs[i * FSTRIDE + j] = F[k];
    }
    // x[b] slice -> smem, coalesced (1600 contiguous floats)
    for (int k = tid; k < NN * PP; k += MAIN_THREADS) {
        int j  = k >> 5;
        int pp = k & 31;
        Xs[j][pp] = x[(size_t)b * NN * PP + k];
    }
    if (tid < PP) {
        int t = x_i[b * PP + tid];
        ts[tid] = t;
        nal[tid] = -alphas[t] * 1.4426950408889634f;    // fold log2(e)
    }
    __syncthreads();

    // a vectors: coalesced mus reads, conflict-free Xs reads (stride 33)
    for (int k = tid; k < NN * PP; k += MAIN_THREADS) {
        int u = k / NN;
        int j = k - u * NN;
        As[u][j] = Xs[j][u] - mus[ts[u] * NN + j];
    }
    __syncthreads();

    // compute: 2 rounds x 16 units x 50 rows = all 800 threads active
    int u0 = tid / 50;
    int i  = tid - u0 * 50;
    #pragma unroll
    for (int r = 0; r < 2; r++) {
        int u = u0 + 16 * r;
        float na = nal[u];
        const float2* frow2 = (const float2*)&Fs[i * FSTRIDE];
        const float2* av2   = (const float2*)As[u];
        float acc = 0.f, s = 0.f;
        #pragma unroll
        for (int jj = 0; jj < NN / 2; jj++) {
            float2 fv = frow2[jj];
            float2 av = av2[jj];
            float e0 = ex2_approx(na * fv.x);
            acc = fmaf(e0, av.x, acc);
            s  += e0;
            float e1 = ex2_approx(na * fv.y);
            acc = fmaf(e1, av.y, acc);
            s  += e1;
        }
        zmat[u][i] = __fdividef(acc, s);
    }
    __syncthreads();

    // reduce over units + fused p*mu_y, direct coalesced store
    if (tid < NN) {
        float s = 0.f;
        #pragma unroll
        for (int u = 0; u < PP; u++) s += zmat[u][tid];
        Z[b * NN + tid] = s + (float)PP * mus[y_i[b] * NN + tid];
    }
}

// ---------------------------------------------------------------------------
extern "C" void kernel_launch(void* const* d_in, const int* in_sizes, int n_in,
                              void* d_out, int out_size) {
    const float* x      = (const float*)d_in[0];  // [512,50,32]
    const int*   x_i    = (const int*)  d_in[1];  // [512,32]
    const int*   y_i    = (const int*)  d_in[2];  // [512]
    const float* g      = (const float*)d_in[3];  // [2500,2500]
    const float* w      = (const float*)d_in[4];  // [2500,1]
    const float* mus    = (const float*)d_in[5];  // [4000,50]
    const float* alphas = (const float*)d_in[6];  // [4000,1]

    float* out  = (float*)d_out;
    float* Z    = out;             // [512,50]
    float* Fout = out + BB * NN;   // [2500]

    f_matvec_kernel<<<(NSQ + 7) / 8, 256>>>(g, w, Fout);
    main_kernel<<<BB, MAIN_THREADS>>>(x, x_i, y_i, mus, alphas, Fout, Z);
}

// round 16
// speedup vs baseline: 1.1604x; 1.1604x over previous
#include <cuda_runtime.h>

#define NN   50
#define PP   32
#define BB   512
#define NSQ  2500
#define FSTRIDE 54          // float2 stride 27, gcd(27,16)=1 -> conflict-free LDS.64
#define UNITS 10
#define K3_THREADS 512
#define TOTAL_UNITS (BB * PP)  // 16384

__device__ __forceinline__ float ex2_approx(float x) {
    float r;
    asm("ex2.approx.f32 %0, %1;" : "=f"(r) : "f"(x));
    return r;
}

// ---------------------------------------------------------------------------
// K1 v4 (PROVEN ~1us, do not touch): F[r] = sum_j g[r,j]*w[j]^2, warp per row,
// register-batched unpredicated LDG.128.
// ---------------------------------------------------------------------------
__global__ __launch_bounds__(256)
void f_matvec_kernel(const float* __restrict__ g,
                     const float* __restrict__ w,
                     float* __restrict__ Fout) {
    __shared__ float4 w2s[625];
    int tid  = threadIdx.x;
    int lane = tid & 31;
    int wid  = tid >> 5;

    const float4* w4 = (const float4*)w;
    for (int j = tid; j < 625; j += 256) {
        float4 wv = w4[j];
        w2s[j] = make_float4(wv.x * wv.x, wv.y * wv.y, wv.z * wv.z, wv.w * wv.w);
    }
    __syncthreads();

    int row = blockIdx.x * 8 + wid;
    if (row >= NSQ) return;
    const float4* grow = (const float4*)g + (size_t)row * 625;

    float4 r[10];
    float acc = 0.f;

    #pragma unroll
    for (int k = 0; k < 10; k++) r[k] = grow[lane + 32 * k];
    #pragma unroll
    for (int k = 0; k < 10; k++) {
        float4 wv = w2s[lane + 32 * k];
        acc = fmaf(r[k].x, wv.x, acc);
        acc = fmaf(r[k].y, wv.y, acc);
        acc = fmaf(r[k].z, wv.z, acc);
        acc = fmaf(r[k].w, wv.w, acc);
    }

    #pragma unroll
    for (int k = 0; k < 10; k++) {
        int idx = 320 + lane + 32 * k;
        r[k] = (idx < 625) ? grow[idx] : make_float4(0.f, 0.f, 0.f, 0.f);
    }
    #pragma unroll
    for (int k = 0; k < 10; k++) {
        int idx = 320 + lane + 32 * k;
        float4 wv = (idx < 625) ? w2s[idx] : make_float4(0.f, 0.f, 0.f, 0.f);
        acc = fmaf(r[k].x, wv.x, acc);
        acc = fmaf(r[k].y, wv.y, acc);
        acc = fmaf(r[k].z, wv.z, acc);
        acc = fmaf(r[k].w, wv.w, acc);
    }

    #pragma unroll
    for (int o = 16; o > 0; o >>= 1)
        acc += __shfl_down_sync(0xffffffffu, acc, o);
    if (lane == 0) Fout[row] = acc;
}

// ---------------------------------------------------------------------------
// K2: Z[b,i] = p * mus[y_i[b], i]   (store-init; must precede K3 atomics)
// ---------------------------------------------------------------------------
__global__ void init_z_kernel(const int* __restrict__ y_i,
                              const float* __restrict__ mus,
                              float* __restrict__ Z) {
    int idx = blockIdx.x * blockDim.x + threadIdx.x;
    if (idx >= BB * NN) return;
    int b = idx / NN;
    int i = idx - b * NN;
    Z[idx] = (float)PP * mus[y_i[b] * NN + i];
}

// ---------------------------------------------------------------------------
// K3: 10 units/block, 512 threads, flattened (u=tid/50, i=tid%50).
// NO launch_bounds reg cap, partial unroll (5), split accumulators ->
// no spills; MUFU (ex2) should be the limiter (~9.6us floor).
// ---------------------------------------------------------------------------
__global__ void main_kernel(const float* __restrict__ x,
                            const int*   __restrict__ x_i,
                            const float* __restrict__ mus,
                            const float* __restrict__ alphas,
                            const float* __restrict__ F,
                            float* __restrict__ Z) {
    __shared__ float Fs[NN * FSTRIDE];
    __shared__ __align__(8) float As[UNITS][52];
    __shared__ float nal[UNITS];
    __shared__ int   ts[UNITS];

    int tid  = threadIdx.x;
    int gid0 = blockIdx.x * UNITS;
    int nu   = TOTAL_UNITS - gid0;
    if (nu > UNITS) nu = UNITS;

    for (int k = tid; k < NSQ; k += K3_THREADS) {
        int i = k / NN;
        int j = k - i * NN;
        Fs[i * FSTRIDE + j] = F[k];
    }
    if (tid < nu) {
        int t = x_i[gid0 + tid];
        ts[tid] = t;
        nal[tid] = -alphas[t] * 1.4426950408889634f;   // fold log2(e)
    }
    __syncthreads();

    for (int k = tid; k < nu * NN; k += K3_THREADS) {
        int u = k / NN;
        int j = k - u * NN;
        int unit = gid0 + u;
        As[u][j] = x[(size_t)(unit >> 5) * NN * PP + j * PP + (unit & 31)]
                 - mus[ts[u] * NN + j];
    }
    __syncthreads();

    if (tid < nu * NN) {
        int u = tid / NN;
        int i = tid - u * NN;
        float na = nal[u];
        const float2* frow2 = (const float2*)&Fs[i * FSTRIDE];
        const float2* av2   = (const float2*)As[u];
        float acc0 = 0.f, acc1 = 0.f, s0 = 0.f, s1 = 0.f;
        #pragma unroll 5
        for (int jj = 0; jj < NN / 2; jj++) {
            float2 fv = frow2[jj];
            float2 av = av2[jj];
            float e0 = ex2_approx(na * fv.x);
            acc0 = fmaf(e0, av.x, acc0);
            s0  += e0;
            float e1 = ex2_approx(na * fv.y);
            acc1 = fmaf(e1, av.y, acc1);
            s1  += e1;
        }
        int b = (gid0 + u) >> 5;
        atomicAdd(&Z[b * NN + i], __fdividef(acc0 + acc1, s0 + s1));
    }
}

// ---------------------------------------------------------------------------
extern "C" void kernel_launch(void* const* d_in, const int* in_sizes, int n_in,
                              void* d_out, int out_size) {
    const float* x      = (const float*)d_in[0];  // [512,50,32]
    const int*   x_i    = (const int*)  d_in[1];  // [512,32]
    const int*   y_i    = (const int*)  d_in[2];  // [512]
    const float* g      = (const float*)d_in[3];  // [2500,2500]
    const float* w      = (const float*)d_in[4];  // [2500,1]
    const float* mus    = (const float*)d_in[5];  // [4000,50]
    const float* alphas = (const float*)d_in[6];  // [4000,1]

    float* out  = (float*)d_out;
    float* Z    = out;             // [512,50]
    float* Fout = out + BB * NN;   // [2500]

    f_matvec_kernel<<<(NSQ + 7) / 8, 256>>>(g, w, Fout);
    init_z_kernel<<<(BB * NN + 255) / 256, 256>>>(y_i, mus, Z);
    main_kernel<<<(TOTAL_UNITS + UNITS - 1) / UNITS, K3_THREADS>>>(x, x_i, mus, alphas, Fout, Z);
}